// round 2
// baseline (speedup 1.0000x reference)
#include <cuda_runtime.h>
#include <cuda_bf16.h>

#define NUM_NODE 8192
#define N_PTS_MAX 20000
#define FEAT_DIM 32
#define TM 256                 // threads per block = rows per block
#define NROWBLK (NUM_NODE / TM)   // 32
#define NS 16                  // j-splits
#define JCHUNK (NUM_NODE / NS) // 512
#define TJ 128                 // j tile staged in smem

#define POS_R2 (0.0375f * 0.0375f)
#define NEG_R2 (0.1f * 0.1f)
#define EPSV 1e-7f
#define BIG2 1e10f             // BIG^2, exactly representable; sqrtf -> 100000.0f exactly

// -------- scratch (allocation-free: __device__ globals) --------
__device__ float  g_sf[NUM_NODE * FEAT_DIM];  // gathered src feats
__device__ float  g_tf[NUM_NODE * FEAT_DIM];  // gathered tgt feats
__device__ float4 g_sp[NUM_NODE];             // src pt (rot applied) xyz, w = src feat |.|^2
__device__ float4 g_tp[NUM_NODE];             // tgt pt xyz, w = tgt feat |.|^2
__device__ float  g_pmax[NUM_NODE * NS];      // per-(row,split) partial max pos d2
__device__ float  g_pmin[NUM_NODE * NS];      // per-(row,split) partial min neg d2

// ---------------- kernel 1: gather + transform + norms ----------------
__global__ void gather_kernel(const float* __restrict__ src_pcd,
                              const float* __restrict__ tgt_pcd,
                              const float* __restrict__ src_feats,
                              const float* __restrict__ tgt_feats,
                              const int* __restrict__ corr,    // int32 (jax default x64 disabled)
                              const float* __restrict__ rot,
                              const float* __restrict__ trans) {
    int i = blockIdx.x * blockDim.x + threadIdx.x;
    if (i >= NUM_NODE) return;
    int ci = corr[2 * i + 0];
    int cj = corr[2 * i + 1];
    // safety clamp: if dtype theory is wrong we get a wrong answer, not a crash
    ci = min(max(ci, 0), N_PTS_MAX - 1);
    cj = min(max(cj, 0), N_PTS_MAX - 1);

    // src point: rot @ p + trans
    float x = src_pcd[3 * ci + 0];
    float y = src_pcd[3 * ci + 1];
    float z = src_pcd[3 * ci + 2];
    float tx = rot[0] * x + rot[1] * y + rot[2] * z + trans[0];
    float ty = rot[3] * x + rot[4] * y + rot[5] * z + trans[1];
    float tz = rot[6] * x + rot[7] * y + rot[8] * z + trans[2];

    float gx = tgt_pcd[3 * cj + 0];
    float gy = tgt_pcd[3 * cj + 1];
    float gz = tgt_pcd[3 * cj + 2];

    float sn = 0.f, tn = 0.f;
#pragma unroll
    for (int k = 0; k < FEAT_DIM; k++) {
        float fs = src_feats[ci * FEAT_DIM + k];
        float ft = tgt_feats[cj * FEAT_DIM + k];
        g_sf[i * FEAT_DIM + k] = fs;
        g_tf[i * FEAT_DIM + k] = ft;
        sn += fs * fs;
        tn += ft * ft;
    }
    g_sp[i] = make_float4(tx, ty, tz, sn);
    g_tp[i] = make_float4(gx, gy, gz, tn);
}

// ---------------- kernel 2: pairwise hardest mining ----------------
__global__ __launch_bounds__(TM) void pair_kernel() {
    const int row = blockIdx.x * TM + threadIdx.x;   // one row per thread
    const int split = blockIdx.y;

    // own row operands in registers
    float fi[FEAT_DIM];
    {
        const float4* f4 = reinterpret_cast<const float4*>(&g_sf[row * FEAT_DIM]);
#pragma unroll
        for (int k = 0; k < FEAT_DIM / 4; k++) {
            float4 v = f4[k];
            fi[4 * k + 0] = v.x; fi[4 * k + 1] = v.y;
            fi[4 * k + 2] = v.z; fi[4 * k + 3] = v.w;
        }
    }
    const float4 pi = g_sp[row];

    float maxpos = 0.f;
    float minneg = BIG2;

    __shared__ float4 s_tp[TJ];
    __shared__ float  s_tf[TJ][FEAT_DIM];   // 16 KB

    const int j0 = split * JCHUNK;
    for (int jt = j0; jt < j0 + JCHUNK; jt += TJ) {
        __syncthreads();
        // cooperative stage: TJ*FEAT_DIM floats = 1024 float4
        {
            const float4* src = reinterpret_cast<const float4*>(&g_tf[jt * FEAT_DIM]);
            float4* dst = reinterpret_cast<float4*>(&s_tf[0][0]);
            for (int v = threadIdx.x; v < TJ * FEAT_DIM / 4; v += TM) dst[v] = src[v];
            for (int v = threadIdx.x; v < TJ; v += TM) s_tp[v] = g_tp[jt + v];
        }
        __syncthreads();

#pragma unroll 4
        for (int jj = 0; jj < TJ; jj++) {
            float4 tp = s_tp[jj];
            float dx = pi.x - tp.x;
            float dy = pi.y - tp.y;
            float dz = pi.z - tp.z;
            float d2p = dx * dx + dy * dy + dz * dz + EPSV;

            const float4* bf = reinterpret_cast<const float4*>(s_tf[jj]);
            float dot = 0.f;
#pragma unroll
            for (int k = 0; k < FEAT_DIM / 4; k++) {
                float4 b = bf[k];
                dot += fi[4 * k + 0] * b.x;
                dot += fi[4 * k + 1] * b.y;
                dot += fi[4 * k + 2] * b.z;
                dot += fi[4 * k + 3] * b.w;
            }
            float d2f = fmaxf(pi.w + tp.w - 2.f * dot, 0.f) + EPSV;

            if (d2p < POS_R2) maxpos = fmaxf(maxpos, d2f);
            if (d2p > NEG_R2) minneg = fminf(minneg, d2f);
        }
    }
    g_pmax[row * NS + split] = maxpos;
    g_pmin[row * NS + split] = minneg;
}

// ---------------- kernel 3: deterministic reduction ----------------
__global__ void reduce_kernel(float* __restrict__ out) {
    __shared__ float ssum[256];
    const int t = threadIdx.x;
    float acc = 0.f;
    for (int r = t; r < NUM_NODE; r += 256) {
        float mp = 0.f, mn = BIG2;
#pragma unroll
        for (int s = 0; s < NS; s++) {
            mp = fmaxf(mp, g_pmax[r * NS + s]);
            mn = fminf(mn, g_pmin[r * NS + s]);
        }
        float fp = sqrtf(mp);           // 0 if no positives
        float cn = sqrtf(mn);           // BIG (exactly) if no negatives
        acc += fmaxf(fp - 0.1f, 0.f) + fmaxf(1.4f - cn, 0.f);
    }
    ssum[t] = acc;
    __syncthreads();
#pragma unroll
    for (int off = 128; off > 0; off >>= 1) {
        if (t < off) ssum[t] += ssum[t + off];
        __syncthreads();
    }
    if (t == 0) out[0] = ssum[0] / (float)NUM_NODE;
}

extern "C" void kernel_launch(void* const* d_in, const int* in_sizes, int n_in,
                              void* d_out, int out_size) {
    const float* src_pcd  = (const float*)d_in[0];
    const float* tgt_pcd  = (const float*)d_in[1];
    const float* src_feats = (const float*)d_in[2];
    const float* tgt_feats = (const float*)d_in[3];
    const int* corr    = (const int*)d_in[4];
    const float* rot   = (const float*)d_in[5];
    const float* trans = (const float*)d_in[6];
    float* out = (float*)d_out;

    gather_kernel<<<NUM_NODE / 256, 256>>>(src_pcd, tgt_pcd, src_feats, tgt_feats,
                                           corr, rot, trans);
    dim3 grid(NROWBLK, NS);
    pair_kernel<<<grid, TM>>>();
    reduce_kernel<<<1, 256>>>(out);
}

// round 3
// speedup vs baseline: 1.3880x; 1.3880x over previous
#include <cuda_runtime.h>
#include <cuda_bf16.h>

#define NUM_NODE 8192
#define N_PTS_MAX 20000
#define FEAT_DIM 32
#define TM 128                    // threads per block
#define ROWS_PER_BLOCK 256        // 2 rows per thread
#define NROWBLK (NUM_NODE / ROWS_PER_BLOCK)   // 32
#define NS 16                     // j-splits -> 512 blocks (single wave on 592 slots)
#define JCHUNK (NUM_NODE / NS)    // 512
#define TJ 128                    // j tile staged in smem

#define POS_R2 (0.0375f * 0.0375f)
#define NEG_R2 (0.1f * 0.1f)
#define EPSV 1e-7f
#define BIG2 1e10f                // BIG^2; sqrtf(1e10f) == 100000.0f exactly

typedef unsigned long long ull;

#define FMA2(d, a, b, c) asm("fma.rn.f32x2 %0, %1, %2, %3;" : "=l"(d) : "l"(a), "l"(b), "l"(c))
#define ADD2(d, a, b)    asm("add.rn.f32x2 %0, %1, %2;"     : "=l"(d) : "l"(a), "l"(b))
#define MUL2(d, a, b)    asm("mul.rn.f32x2 %0, %1, %2;"     : "=l"(d) : "l"(a), "l"(b))
#define PACK2(d, lo, hi) asm("mov.b64 %0, {%1, %2};" : "=l"(d) : "f"(lo), "f"(hi))
#define UNPACK2(lo, hi, s) asm("mov.b64 {%0, %1}, %2;" : "=f"(lo), "=f"(hi) : "l"(s))

// -------- scratch (allocation-free: __device__ globals) --------
__device__ float  g_sf[NUM_NODE * FEAT_DIM];      // gathered src feats (k-contiguous)
__device__ float  g_tf[NUM_NODE * FEAT_DIM];      // gathered tgt feats (k-contiguous)
__device__ float4 g_sp[NUM_NODE];                 // src pt xyz (rot applied), w = |feat|^2
__device__ float4 g_tp2[NUM_NODE * 2];            // tgt pt DUPLICATED: (x,x,y,y),(z,z,w,w)
__device__ float  g_pmax[NUM_NODE * NS];
__device__ float  g_pmin[NUM_NODE * NS];

// ---------------- kernel 1: warp-per-node gather ----------------
__global__ void gather_kernel(const float* __restrict__ src_pcd,
                              const float* __restrict__ tgt_pcd,
                              const float* __restrict__ src_feats,
                              const float* __restrict__ tgt_feats,
                              const int* __restrict__ corr,
                              const float* __restrict__ rot,
                              const float* __restrict__ trans) {
    int node = (blockIdx.x * blockDim.x + threadIdx.x) >> 5;
    int lane = threadIdx.x & 31;
    if (node >= NUM_NODE) return;
    int ci = corr[2 * node + 0];
    int cj = corr[2 * node + 1];
    ci = min(max(ci, 0), N_PTS_MAX - 1);
    cj = min(max(cj, 0), N_PTS_MAX - 1);

    float fs = src_feats[ci * FEAT_DIM + lane];
    float ft = tgt_feats[cj * FEAT_DIM + lane];
    g_sf[node * FEAT_DIM + lane] = fs;
    g_tf[node * FEAT_DIM + lane] = ft;

    float sn = fs * fs, tn = ft * ft;
#pragma unroll
    for (int off = 16; off > 0; off >>= 1) {
        sn += __shfl_xor_sync(0xffffffffu, sn, off);
        tn += __shfl_xor_sync(0xffffffffu, tn, off);
    }

    if (lane == 0) {
        float x = src_pcd[3 * ci + 0];
        float y = src_pcd[3 * ci + 1];
        float z = src_pcd[3 * ci + 2];
        float tx = rot[0] * x + rot[1] * y + rot[2] * z + trans[0];
        float ty = rot[3] * x + rot[4] * y + rot[5] * z + trans[1];
        float tz = rot[6] * x + rot[7] * y + rot[8] * z + trans[2];
        g_sp[node] = make_float4(tx, ty, tz, sn);

        float gx = tgt_pcd[3 * cj + 0];
        float gy = tgt_pcd[3 * cj + 1];
        float gz = tgt_pcd[3 * cj + 2];
        g_tp2[2 * node + 0] = make_float4(gx, gx, gy, gy);
        g_tp2[2 * node + 1] = make_float4(gz, gz, tn, tn);
    }
}

// ---------------- kernel 2: pairwise hardest mining (f32x2) ----------------
__global__ __launch_bounds__(TM) void pair_kernel() {
    const int t = threadIdx.x;
    const int row0 = blockIdx.x * ROWS_PER_BLOCK + t;       // rows row0, row0+TM
    const int row1 = row0 + TM;
    const int split = blockIdx.y;

    // k-packed own features for both rows (adjacent-k packing = natural layout)
    ull fi0[FEAT_DIM / 2], fi1[FEAT_DIM / 2];
    {
        const ull* a = reinterpret_cast<const ull*>(&g_sf[row0 * FEAT_DIM]);
        const ull* b = reinterpret_cast<const ull*>(&g_sf[row1 * FEAT_DIM]);
#pragma unroll
        for (int k = 0; k < FEAT_DIM / 2; k++) { fi0[k] = a[k]; fi1[k] = b[k]; }
    }
    const float4 p0 = g_sp[row0];
    const float4 p1 = g_sp[row1];
    // row-packed negated source point coords
    ull npx2, npy2, npz2;
    PACK2(npx2, -p0.x, -p1.x);
    PACK2(npy2, -p0.y, -p1.y);
    PACK2(npz2, -p0.z, -p1.z);

    float maxpos0 = 0.f, maxpos1 = 0.f;
    float minneg0 = BIG2, minneg1 = BIG2;

    __shared__ ulonglong2 s_tp[TJ * 2];             // 32B per jj: (x,x,y,y),(z,z,w,w)
    __shared__ float s_tf[TJ][FEAT_DIM];            // 16 KB, k-contiguous

    const int j0 = split * JCHUNK;
    for (int jt = j0; jt < j0 + JCHUNK; jt += TJ) {
        __syncthreads();
        {
            const float4* src = reinterpret_cast<const float4*>(&g_tf[jt * FEAT_DIM]);
            float4* dst = reinterpret_cast<float4*>(&s_tf[0][0]);
            for (int v = t; v < TJ * FEAT_DIM / 4; v += TM) dst[v] = src[v];
            const ulonglong2* ps = reinterpret_cast<const ulonglong2*>(&g_tp2[2 * jt]);
            for (int v = t; v < TJ * 2; v += TM) s_tp[v] = ps[v];
        }
        __syncthreads();

#pragma unroll 4
        for (int jj = 0; jj < TJ; jj++) {
            ulonglong2 qa = s_tp[2 * jj + 0];
            ulonglong2 qb = s_tp[2 * jj + 1];
            ull txx = qa.x, tyy = qa.y, tzz = qb.x, tww = qb.y;

            // packed point distance for both rows
            ull dx2, dy2, dz2, d2p2;
            ADD2(dx2, txx, npx2);
            ADD2(dy2, tyy, npy2);
            ADD2(dz2, tzz, npz2);
            MUL2(d2p2, dx2, dx2);
            FMA2(d2p2, dy2, dy2, d2p2);
            FMA2(d2p2, dz2, dz2, d2p2);
            float d2p0, d2p1;
            UNPACK2(d2p0, d2p1, d2p2);

            // k-packed dot products (each LDS.128 = 2 packed b operands)
            const ulonglong2* bf = reinterpret_cast<const ulonglong2*>(s_tf[jj]);
            ull dot0 = 0, dot1 = 0;
#pragma unroll
            for (int k = 0; k < FEAT_DIM / 4; k++) {
                ulonglong2 b = bf[k];
                FMA2(dot0, fi0[2 * k + 0], b.x, dot0);
                FMA2(dot0, fi0[2 * k + 1], b.y, dot0);
                FMA2(dot1, fi1[2 * k + 0], b.x, dot1);
                FMA2(dot1, fi1[2 * k + 1], b.y, dot1);
            }
            float tn, tn_dup;
            UNPACK2(tn, tn_dup, tww);
            float a0, c0, a1, c1;
            UNPACK2(a0, c0, dot0);
            UNPACK2(a1, c1, dot1);
            float d2f0 = fmaf(-2.f, a0 + c0, p0.w + tn);
            float d2f1 = fmaf(-2.f, a1 + c1, p1.w + tn);

            if (d2p0 < POS_R2) maxpos0 = fmaxf(maxpos0, d2f0);
            if (d2p0 > NEG_R2) minneg0 = fminf(minneg0, d2f0);
            if (d2p1 < POS_R2) maxpos1 = fmaxf(maxpos1, d2f1);
            if (d2p1 > NEG_R2) minneg1 = fminf(minneg1, d2f1);
        }
    }
    g_pmax[row0 * NS + split] = maxpos0;
    g_pmin[row0 * NS + split] = minneg0;
    g_pmax[row1 * NS + split] = maxpos1;
    g_pmin[row1 * NS + split] = minneg1;
}

// ---------------- kernel 3: deterministic reduction ----------------
__global__ void reduce_kernel(float* __restrict__ out) {
    __shared__ float ssum[256];
    const int t = threadIdx.x;
    float acc = 0.f;
    for (int r = t; r < NUM_NODE; r += 256) {
        float mp = 0.f, mn = BIG2;
#pragma unroll
        for (int s = 0; s < NS; s++) {
            mp = fmaxf(mp, g_pmax[r * NS + s]);
            mn = fminf(mn, g_pmin[r * NS + s]);
        }
        float fp = sqrtf(fmaxf(mp, 0.f) + EPSV);
        float cn = sqrtf(fmaxf(mn, 0.f) + EPSV);
        acc += fmaxf(fp - 0.1f, 0.f) + fmaxf(1.4f - cn, 0.f);
    }
    ssum[t] = acc;
    __syncthreads();
#pragma unroll
    for (int off = 128; off > 0; off >>= 1) {
        if (t < off) ssum[t] += ssum[t + off];
        __syncthreads();
    }
    if (t == 0) out[0] = ssum[0] / (float)NUM_NODE;
}

extern "C" void kernel_launch(void* const* d_in, const int* in_sizes, int n_in,
                              void* d_out, int out_size) {
    const float* src_pcd  = (const float*)d_in[0];
    const float* tgt_pcd  = (const float*)d_in[1];
    const float* src_feats = (const float*)d_in[2];
    const float* tgt_feats = (const float*)d_in[3];
    const int* corr    = (const int*)d_in[4];
    const float* rot   = (const float*)d_in[5];
    const float* trans = (const float*)d_in[6];
    float* out = (float*)d_out;

    gather_kernel<<<NUM_NODE * 32 / 256, 256>>>(src_pcd, tgt_pcd, src_feats, tgt_feats,
                                                corr, rot, trans);
    dim3 grid(NROWBLK, NS);
    pair_kernel<<<grid, TM>>>();
    reduce_kernel<<<1, 256>>>(out);
}

// round 4
// speedup vs baseline: 1.8880x; 1.3602x over previous
#include <cuda_runtime.h>
#include <cuda_bf16.h>

#define NUM_NODE 8192
#define N_PTS_MAX 20000
#define FEAT_DIM 32
#define TM 128                    // threads per block
#define ROWS_PER_BLOCK 256        // 2 rows per thread
#define NROWBLK (NUM_NODE / ROWS_PER_BLOCK)   // 32
#define NS 16                     // j-splits -> 512 blocks
#define JCHUNK (NUM_NODE / NS)    // 512
#define TJ 128                    // j tile staged in smem

#define POS_R2 (0.0375f * 0.0375f)
#define NEG_R2 (0.1f * 0.1f)
#define EPSV 1e-7f
#define BIG2 1e10f                // BIG^2; sqrtf(1e10f) == 100000.0f exactly

typedef unsigned long long ull;

#define FMA2(d, a, b, c) asm("fma.rn.f32x2 %0, %1, %2, %3;" : "=l"(d) : "l"(a), "l"(b), "l"(c))
#define ADD2(d, a, b)    asm("add.rn.f32x2 %0, %1, %2;"     : "=l"(d) : "l"(a), "l"(b))
#define MUL2(d, a, b)    asm("mul.rn.f32x2 %0, %1, %2;"     : "=l"(d) : "l"(a), "l"(b))
#define PACK2(d, lo, hi) asm("mov.b64 %0, {%1, %2};" : "=l"(d) : "f"(lo), "f"(hi))
#define UNPACK2(lo, hi, s) asm("mov.b64 {%0, %1}, %2;" : "=f"(lo), "=f"(hi) : "l"(s))

// -------- scratch (allocation-free: __device__ globals) --------
__device__ float  g_sf[NUM_NODE * FEAT_DIM];
__device__ float  g_tf[NUM_NODE * FEAT_DIM];
__device__ float4 g_sp[NUM_NODE];                 // src pt xyz (rot applied), w = |feat|^2
__device__ float4 g_tp2[NUM_NODE * 2];            // tgt pt duplicated: (x,x,y,y),(z,z,w,w)
__device__ float  g_pmax[NUM_NODE * NS];
__device__ float  g_pmin[NUM_NODE * NS];
__device__ float  g_partial[NROWBLK];             // stage-1 reduce partials

// ---------------- kernel 1: warp-per-node gather ----------------
__global__ void gather_kernel(const float* __restrict__ src_pcd,
                              const float* __restrict__ tgt_pcd,
                              const float* __restrict__ src_feats,
                              const float* __restrict__ tgt_feats,
                              const int* __restrict__ corr,
                              const float* __restrict__ rot,
                              const float* __restrict__ trans) {
    int node = (blockIdx.x * blockDim.x + threadIdx.x) >> 5;
    int lane = threadIdx.x & 31;
    if (node >= NUM_NODE) return;
    int ci = corr[2 * node + 0];
    int cj = corr[2 * node + 1];
    ci = min(max(ci, 0), N_PTS_MAX - 1);
    cj = min(max(cj, 0), N_PTS_MAX - 1);

    float fs = src_feats[ci * FEAT_DIM + lane];
    float ft = tgt_feats[cj * FEAT_DIM + lane];
    g_sf[node * FEAT_DIM + lane] = fs;
    g_tf[node * FEAT_DIM + lane] = ft;

    float sn = fs * fs, tn = ft * ft;
#pragma unroll
    for (int off = 16; off > 0; off >>= 1) {
        sn += __shfl_xor_sync(0xffffffffu, sn, off);
        tn += __shfl_xor_sync(0xffffffffu, tn, off);
    }

    if (lane == 0) {
        float x = src_pcd[3 * ci + 0];
        float y = src_pcd[3 * ci + 1];
        float z = src_pcd[3 * ci + 2];
        float tx = rot[0] * x + rot[1] * y + rot[2] * z + trans[0];
        float ty = rot[3] * x + rot[4] * y + rot[5] * z + trans[1];
        float tz = rot[6] * x + rot[7] * y + rot[8] * z + trans[2];
        g_sp[node] = make_float4(tx, ty, tz, sn);

        float gx = tgt_pcd[3 * cj + 0];
        float gy = tgt_pcd[3 * cj + 1];
        float gz = tgt_pcd[3 * cj + 2];
        g_tp2[2 * node + 0] = make_float4(gx, gx, gy, gy);
        g_tp2[2 * node + 1] = make_float4(gz, gz, tn, tn);
    }
}

// ---------------- kernel 2: pairwise hardest mining (f32x2, split chains) ----------------
__global__ __launch_bounds__(TM) void pair_kernel() {
    const int t = threadIdx.x;
    const int row0 = blockIdx.x * ROWS_PER_BLOCK + t;
    const int row1 = row0 + TM;
    const int split = blockIdx.y;

    // k-packed own features for both rows
    ull fi0[FEAT_DIM / 2], fi1[FEAT_DIM / 2];
    {
        const ull* a = reinterpret_cast<const ull*>(&g_sf[row0 * FEAT_DIM]);
        const ull* b = reinterpret_cast<const ull*>(&g_sf[row1 * FEAT_DIM]);
#pragma unroll
        for (int k = 0; k < FEAT_DIM / 2; k++) { fi0[k] = a[k]; fi1[k] = b[k]; }
    }
    const float4 p0 = g_sp[row0];
    const float4 p1 = g_sp[row1];
    ull npx2, npy2, npz2;
    PACK2(npx2, -p0.x, -p1.x);
    PACK2(npy2, -p0.y, -p1.y);
    PACK2(npz2, -p0.z, -p1.z);
    const float pw0 = p0.w, pw1 = p1.w;

    float maxpos0 = 0.f, maxpos1 = 0.f;
    float minneg0 = BIG2, minneg1 = BIG2;

    __shared__ ulonglong2 s_tp[TJ * 2];             // 32B per jj
    __shared__ float s_tf[TJ][FEAT_DIM];            // 16 KB

    const int j0 = split * JCHUNK;
    for (int jt = j0; jt < j0 + JCHUNK; jt += TJ) {
        __syncthreads();
        {
            const float4* src = reinterpret_cast<const float4*>(&g_tf[jt * FEAT_DIM]);
            float4* dst = reinterpret_cast<float4*>(&s_tf[0][0]);
            for (int v = t; v < TJ * FEAT_DIM / 4; v += TM) dst[v] = src[v];
            const ulonglong2* ps = reinterpret_cast<const ulonglong2*>(&g_tp2[2 * jt]);
            for (int v = t; v < TJ * 2; v += TM) s_tp[v] = ps[v];
        }
        __syncthreads();

#pragma unroll 4
        for (int jj = 0; jj < TJ; jj++) {
            // ---- loads first (front-batch for MLP) ----
            ulonglong2 qa = s_tp[2 * jj + 0];
            ulonglong2 qb = s_tp[2 * jj + 1];
            const ulonglong2* bf = reinterpret_cast<const ulonglong2*>(s_tf[jj]);
            ulonglong2 b0 = bf[0], b1 = bf[1], b2 = bf[2], b3 = bf[3];
            ulonglong2 b4 = bf[4], b5 = bf[5], b6 = bf[6], b7 = bf[7];

            // ---- packed point distance (both rows) ----
            ull dx2, dy2, dz2, d2p2;
            ADD2(dx2, qa.x, npx2);
            ADD2(dy2, qa.y, npy2);
            ADD2(dz2, qb.x, npz2);
            MUL2(d2p2, dx2, dx2);
            FMA2(d2p2, dy2, dy2, d2p2);
            FMA2(d2p2, dz2, dz2, d2p2);

            // ---- 4 independent dot chains, depth 8 ----
            ull d0a = 0, d0b = 0, d1a = 0, d1b = 0;
            FMA2(d0a, fi0[0],  b0.x, d0a); FMA2(d0b, fi0[1],  b0.y, d0b);
            FMA2(d1a, fi1[0],  b0.x, d1a); FMA2(d1b, fi1[1],  b0.y, d1b);
            FMA2(d0a, fi0[2],  b1.x, d0a); FMA2(d0b, fi0[3],  b1.y, d0b);
            FMA2(d1a, fi1[2],  b1.x, d1a); FMA2(d1b, fi1[3],  b1.y, d1b);
            FMA2(d0a, fi0[4],  b2.x, d0a); FMA2(d0b, fi0[5],  b2.y, d0b);
            FMA2(d1a, fi1[4],  b2.x, d1a); FMA2(d1b, fi1[5],  b2.y, d1b);
            FMA2(d0a, fi0[6],  b3.x, d0a); FMA2(d0b, fi0[7],  b3.y, d0b);
            FMA2(d1a, fi1[6],  b3.x, d1a); FMA2(d1b, fi1[7],  b3.y, d1b);
            FMA2(d0a, fi0[8],  b4.x, d0a); FMA2(d0b, fi0[9],  b4.y, d0b);
            FMA2(d1a, fi1[8],  b4.x, d1a); FMA2(d1b, fi1[9],  b4.y, d1b);
            FMA2(d0a, fi0[10], b5.x, d0a); FMA2(d0b, fi0[11], b5.y, d0b);
            FMA2(d1a, fi1[10], b5.x, d1a); FMA2(d1b, fi1[11], b5.y, d1b);
            FMA2(d0a, fi0[12], b6.x, d0a); FMA2(d0b, fi0[13], b6.y, d0b);
            FMA2(d1a, fi1[12], b6.x, d1a); FMA2(d1b, fi1[13], b6.y, d1b);
            FMA2(d0a, fi0[14], b7.x, d0a); FMA2(d0b, fi0[15], b7.y, d0b);
            FMA2(d1a, fi1[14], b7.x, d1a); FMA2(d1b, fi1[15], b7.y, d1b);

            ull s0, s1;
            ADD2(s0, d0a, d0b);
            ADD2(s1, d1a, d1b);
            float d2p0, d2p1;
            UNPACK2(d2p0, d2p1, d2p2);
            float tn, tn_dup;
            UNPACK2(tn, tn_dup, qb.y);
            float a0, c0, a1, c1;
            UNPACK2(a0, c0, s0);
            UNPACK2(a1, c1, s1);
            float d2f0 = fmaf(-2.f, a0 + c0, pw0 + tn);
            float d2f1 = fmaf(-2.f, a1 + c1, pw1 + tn);

            maxpos0 = fmaxf(maxpos0, d2p0 < POS_R2 ? d2f0 : 0.f);
            minneg0 = fminf(minneg0, d2p0 > NEG_R2 ? d2f0 : BIG2);
            maxpos1 = fmaxf(maxpos1, d2p1 < POS_R2 ? d2f1 : 0.f);
            minneg1 = fminf(minneg1, d2p1 > NEG_R2 ? d2f1 : BIG2);
        }
    }
    g_pmax[row0 * NS + split] = maxpos0;
    g_pmin[row0 * NS + split] = minneg0;
    g_pmax[row1 * NS + split] = maxpos1;
    g_pmin[row1 * NS + split] = minneg1;
}

// ---------------- kernel 3a: per-rowblock reduction ----------------
__global__ void reduce1_kernel() {
    __shared__ float ssum[256];
    const int t = threadIdx.x;
    const int r = blockIdx.x * 256 + t;          // one row per thread
    float mp = 0.f, mn = BIG2;
#pragma unroll
    for (int s = 0; s < NS; s++) {
        mp = fmaxf(mp, g_pmax[r * NS + s]);
        mn = fminf(mn, g_pmin[r * NS + s]);
    }
    float fp = sqrtf(fmaxf(mp, 0.f) + EPSV);
    float cn = sqrtf(fmaxf(mn, 0.f) + EPSV);
    float acc = fmaxf(fp - 0.1f, 0.f) + fmaxf(1.4f - cn, 0.f);
    ssum[t] = acc;
    __syncthreads();
#pragma unroll
    for (int off = 128; off > 0; off >>= 1) {
        if (t < off) ssum[t] += ssum[t + off];
        __syncthreads();
    }
    if (t == 0) g_partial[blockIdx.x] = ssum[0];
}

// ---------------- kernel 3b: final sum (1 warp) ----------------
__global__ void reduce2_kernel(float* __restrict__ out) {
    int t = threadIdx.x;
    float v = (t < NROWBLK) ? g_partial[t] : 0.f;
#pragma unroll
    for (int off = 16; off > 0; off >>= 1)
        v += __shfl_xor_sync(0xffffffffu, v, off);
    if (t == 0) out[0] = v / (float)NUM_NODE;
}

extern "C" void kernel_launch(void* const* d_in, const int* in_sizes, int n_in,
                              void* d_out, int out_size) {
    const float* src_pcd  = (const float*)d_in[0];
    const float* tgt_pcd  = (const float*)d_in[1];
    const float* src_feats = (const float*)d_in[2];
    const float* tgt_feats = (const float*)d_in[3];
    const int* corr    = (const int*)d_in[4];
    const float* rot   = (const float*)d_in[5];
    const float* trans = (const float*)d_in[6];
    float* out = (float*)d_out;

    gather_kernel<<<NUM_NODE * 32 / 256, 256>>>(src_pcd, tgt_pcd, src_feats, tgt_feats,
                                                corr, rot, trans);
    dim3 grid(NROWBLK, NS);
    pair_kernel<<<grid, TM>>>();
    reduce1_kernel<<<NUM_NODE / 256, 256>>>();
    reduce2_kernel<<<1, 32>>>(out);
}

// round 6
// speedup vs baseline: 2.8805x; 1.5257x over previous
#include <cuda_runtime.h>
#include <cstdint>

#define NUM_NODE 8192
#define N_PTS_MAX 20000
#define FEAT_DIM 32
#define TILE 128
#define NTILE (NUM_NODE / TILE)   // 64 -> grid 64x64
#define PAD 36                    // smem row stride (floats), conflict-free fragments

#define POS_R2 (0.0375f * 0.0375f)
#define NEG_R2 (0.1f * 0.1f)
#define EPSV 1e-7f
#define BIG2 1e10f                // sqrtf(1e10f + eps) == 100000.0f exactly

typedef unsigned long long ull;

#define FMA2(d, a, b, c) asm("fma.rn.f32x2 %0, %1, %2, %3;" : "=l"(d) : "l"(a), "l"(b), "l"(c))
#define ADD2(d, a, b)    asm("add.rn.f32x2 %0, %1, %2;"     : "=l"(d) : "l"(a), "l"(b))
#define MUL2(d, a, b)    asm("mul.rn.f32x2 %0, %1, %2;"     : "=l"(d) : "l"(a), "l"(b))
#define PACK2(d, lo, hi) asm("mov.b64 %0, {%1, %2};" : "=l"(d) : "f"(lo), "f"(hi))
#define UNPACK2(lo, hi, s) asm("mov.b64 {%0, %1}, %2;" : "=f"(lo), "=f"(hi) : "l"(s))

// -------- scratch (allocation-free: __device__ globals) --------
__device__ float  g_sf[NUM_NODE * FEAT_DIM];   // gathered src feats, tf32-rounded bits
__device__ float  g_tf[NUM_NODE * FEAT_DIM];   // gathered tgt feats, tf32-rounded bits
__device__ float4 g_sp[NUM_NODE];              // src pt xyz (rot applied), w = |feat|^2 (exact)
__device__ float4 g_tp2[NUM_NODE * 2];         // tgt pt duplicated: (x,x,y,y),(z,z,w,w)
__device__ float  g_pmax[NUM_NODE * NTILE];
__device__ float  g_pmin[NUM_NODE * NTILE];
__device__ float  g_partial[32];

// ---------------- kernel 1: warp-per-node gather (+ tf32 rounding) ----------------
__global__ void gather_kernel(const float* __restrict__ src_pcd,
                              const float* __restrict__ tgt_pcd,
                              const float* __restrict__ src_feats,
                              const float* __restrict__ tgt_feats,
                              const int* __restrict__ corr,
                              const float* __restrict__ rot,
                              const float* __restrict__ trans) {
    int node = (blockIdx.x * blockDim.x + threadIdx.x) >> 5;
    int lane = threadIdx.x & 31;
    if (node >= NUM_NODE) return;
    int ci = corr[2 * node + 0];
    int cj = corr[2 * node + 1];
    ci = min(max(ci, 0), N_PTS_MAX - 1);
    cj = min(max(cj, 0), N_PTS_MAX - 1);

    float fs = src_feats[ci * FEAT_DIM + lane];
    float ft = tgt_feats[cj * FEAT_DIM + lane];

    // store tf32-rounded bits for the MMA operands
    uint32_t fsb, ftb;
    asm("cvt.rna.tf32.f32 %0, %1;" : "=r"(fsb) : "f"(fs));
    asm("cvt.rna.tf32.f32 %0, %1;" : "=r"(ftb) : "f"(ft));
    g_sf[node * FEAT_DIM + lane] = __uint_as_float(fsb);
    g_tf[node * FEAT_DIM + lane] = __uint_as_float(ftb);

    // norms from EXACT fp32 values (matches reference)
    float sn = fs * fs, tn = ft * ft;
#pragma unroll
    for (int off = 16; off > 0; off >>= 1) {
        sn += __shfl_xor_sync(0xffffffffu, sn, off);
        tn += __shfl_xor_sync(0xffffffffu, tn, off);
    }

    if (lane == 0) {
        float x = src_pcd[3 * ci + 0];
        float y = src_pcd[3 * ci + 1];
        float z = src_pcd[3 * ci + 2];
        float tx = rot[0] * x + rot[1] * y + rot[2] * z + trans[0];
        float ty = rot[3] * x + rot[4] * y + rot[5] * z + trans[1];
        float tz = rot[6] * x + rot[7] * y + rot[8] * z + trans[2];
        g_sp[node] = make_float4(tx, ty, tz, sn);

        float gx = tgt_pcd[3 * cj + 0];
        float gy = tgt_pcd[3 * cj + 1];
        float gz = tgt_pcd[3 * cj + 2];
        g_tp2[2 * node + 0] = make_float4(gx, gx, gy, gy);
        g_tp2[2 * node + 1] = make_float4(gz, gz, tn, tn);
    }
}

// ---------------- kernel 2: tf32 mma.sync Gram tile + hardest-mining epilogue ----------------
__global__ __launch_bounds__(128) void mma_pair_kernel() {
    __shared__ float sA[TILE * PAD];          // 18 KB
    __shared__ float sB[TILE * PAD];          // 18 KB
    __shared__ ulonglong2 sTPd[TILE * 2];     // 4 KB duplicated tgt pts

    const int t  = threadIdx.x;
    const int w  = t >> 5;
    const int l  = t & 31;
    const int g  = l >> 2;        // group id (0..7)
    const int tq = l & 3;         // thread-in-group (0..3)
    const int i0 = blockIdx.y * TILE;
    const int j0 = blockIdx.x * TILE;

    // ---- stage tiles (coalesced: 8 lanes per row) ----
    {
        const float4* gA = reinterpret_cast<const float4*>(&g_sf[i0 * FEAT_DIM]);
        const float4* gB = reinterpret_cast<const float4*>(&g_tf[j0 * FEAT_DIM]);
#pragma unroll
        for (int idx = t; idx < TILE * 8; idx += 128) {
            int row = idx >> 3, c = idx & 7;
            *reinterpret_cast<float4*>(&sA[row * PAD + c * 4]) = gA[idx];
            *reinterpret_cast<float4*>(&sB[row * PAD + c * 4]) = gB[idx];
        }
        const ulonglong2* ps = reinterpret_cast<const ulonglong2*>(&g_tp2[2 * j0]);
        for (int v = t; v < TILE * 2; v += 128) sTPd[v] = ps[v];
    }
    __syncthreads();

    // ---- MMA: warp w owns rows [w*32, w*32+32), all 128 cols ----
    float acc[2][16][4];
#pragma unroll
    for (int mf = 0; mf < 2; mf++)
#pragma unroll
        for (int nf = 0; nf < 16; nf++)
#pragma unroll
            for (int r = 0; r < 4; r++) acc[mf][nf][r] = 0.f;

    const int rbase = w * 32;
#pragma unroll
    for (int ks = 0; ks < 4; ks++) {
        const int k0 = ks * 8 + tq;
        uint32_t a[2][4];
#pragma unroll
        for (int mf = 0; mf < 2; mf++) {
            int r0 = rbase + mf * 16 + g;
            a[mf][0] = __float_as_uint(sA[r0 * PAD + k0]);
            a[mf][1] = __float_as_uint(sA[(r0 + 8) * PAD + k0]);
            a[mf][2] = __float_as_uint(sA[r0 * PAD + k0 + 4]);
            a[mf][3] = __float_as_uint(sA[(r0 + 8) * PAD + k0 + 4]);
        }
#pragma unroll
        for (int nf = 0; nf < 16; nf++) {
            int jr = nf * 8 + g;
            uint32_t b0 = __float_as_uint(sB[jr * PAD + k0]);
            uint32_t b1 = __float_as_uint(sB[jr * PAD + k0 + 4]);
#pragma unroll
            for (int mf = 0; mf < 2; mf++) {
                asm volatile(
                    "mma.sync.aligned.m16n8k8.row.col.f32.tf32.tf32.f32 "
                    "{%0,%1,%2,%3}, {%4,%5,%6,%7}, {%8,%9}, {%0,%1,%2,%3};"
                    : "+f"(acc[mf][nf][0]), "+f"(acc[mf][nf][1]),
                      "+f"(acc[mf][nf][2]), "+f"(acc[mf][nf][3])
                    : "r"(a[mf][0]), "r"(a[mf][1]), "r"(a[mf][2]), "r"(a[mf][3]),
                      "r"(b0), "r"(b1));
            }
        }
    }

    // ---- epilogue: exact fp32 point masks + d2f from Gram values ----
    ull npx2[2], npy2[2], npz2[2], sn2[2];
#pragma unroll
    for (int mf = 0; mf < 2; mf++) {
        float4 spA = g_sp[i0 + rbase + mf * 16 + g];
        float4 spB = g_sp[i0 + rbase + mf * 16 + g + 8];
        PACK2(npx2[mf], -spA.x, -spB.x);
        PACK2(npy2[mf], -spA.y, -spB.y);
        PACK2(npz2[mf], -spA.z, -spB.z);
        PACK2(sn2[mf], spA.w, spB.w);
    }
    ull m2; PACK2(m2, -2.f, -2.f);

    float mp[4] = {0.f, 0.f, 0.f, 0.f};
    float mn[4] = {BIG2, BIG2, BIG2, BIG2};

#pragma unroll
    for (int nf = 0; nf < 16; nf++) {
#pragma unroll
        for (int sub = 0; sub < 2; sub++) {
            int col = nf * 8 + tq * 2 + sub;
            ulonglong2 qa = sTPd[2 * col];       // (x,x),(y,y)
            ulonglong2 qb = sTPd[2 * col + 1];   // (z,z),(w,w)
#pragma unroll
            for (int mf = 0; mf < 2; mf++) {
                ull G2; PACK2(G2, acc[mf][nf][sub], acc[mf][nf][2 + sub]);
                ull dx2, dy2, dz2, d2p2, sntn2, d2f2;
                ADD2(dx2, qa.x, npx2[mf]);
                ADD2(dy2, qa.y, npy2[mf]);
                ADD2(dz2, qb.x, npz2[mf]);
                MUL2(d2p2, dx2, dx2);
                FMA2(d2p2, dy2, dy2, d2p2);
                FMA2(d2p2, dz2, dz2, d2p2);
                ADD2(sntn2, sn2[mf], qb.y);
                FMA2(d2f2, m2, G2, sntn2);
                float p0, p1, f0, f1;
                UNPACK2(p0, p1, d2p2);
                UNPACK2(f0, f1, d2f2);
                mp[2 * mf]     = fmaxf(mp[2 * mf],     p0 < POS_R2 ? f0 : 0.f);
                mn[2 * mf]     = fminf(mn[2 * mf],     p0 > NEG_R2 ? f0 : BIG2);
                mp[2 * mf + 1] = fmaxf(mp[2 * mf + 1], p1 < POS_R2 ? f1 : 0.f);
                mn[2 * mf + 1] = fminf(mn[2 * mf + 1], p1 > NEG_R2 ? f1 : BIG2);
            }
        }
    }

    // quad-reduce across the 4 lanes sharing the same rows (tq dimension)
#pragma unroll
    for (int q = 0; q < 4; q++) {
        mp[q] = fmaxf(mp[q], __shfl_xor_sync(0xffffffffu, mp[q], 1));
        mp[q] = fmaxf(mp[q], __shfl_xor_sync(0xffffffffu, mp[q], 2));
        mn[q] = fminf(mn[q], __shfl_xor_sync(0xffffffffu, mn[q], 1));
        mn[q] = fminf(mn[q], __shfl_xor_sync(0xffffffffu, mn[q], 2));
    }
    if (tq == 0) {
#pragma unroll
        for (int q = 0; q < 4; q++) {
            int mf = q >> 1;
            int row = i0 + rbase + mf * 16 + g + (q & 1) * 8;
            g_pmax[row * NTILE + blockIdx.x] = mp[q];
            g_pmin[row * NTILE + blockIdx.x] = mn[q];
        }
    }
}

// ---------------- kernel 3a: per-row reduction over j-tiles ----------------
__global__ void reduce1_kernel() {
    __shared__ float ssum[256];
    const int t = threadIdx.x;
    const int r = blockIdx.x * 256 + t;
    float mp = 0.f, mn = BIG2;
#pragma unroll 8
    for (int s = 0; s < NTILE; s++) {
        mp = fmaxf(mp, g_pmax[r * NTILE + s]);
        mn = fminf(mn, g_pmin[r * NTILE + s]);
    }
    float fp = sqrtf(fmaxf(mp, 0.f) + EPSV);
    float cn = sqrtf(fmaxf(mn, 0.f) + EPSV);
    ssum[t] = fmaxf(fp - 0.1f, 0.f) + fmaxf(1.4f - cn, 0.f);
    __syncthreads();
#pragma unroll
    for (int off = 128; off > 0; off >>= 1) {
        if (t < off) ssum[t] += ssum[t + off];
        __syncthreads();
    }
    if (t == 0) g_partial[blockIdx.x] = ssum[0];
}

// ---------------- kernel 3b: final sum (1 warp) ----------------
__global__ void reduce2_kernel(float* __restrict__ out) {
    int t = threadIdx.x;
    float v = (t < 32) ? g_partial[t] : 0.f;
#pragma unroll
    for (int off = 16; off > 0; off >>= 1)
        v += __shfl_xor_sync(0xffffffffu, v, off);
    if (t == 0) out[0] = v / (float)NUM_NODE;
}

extern "C" void kernel_launch(void* const* d_in, const int* in_sizes, int n_in,
                              void* d_out, int out_size) {
    const float* src_pcd  = (const float*)d_in[0];
    const float* tgt_pcd  = (const float*)d_in[1];
    const float* src_feats = (const float*)d_in[2];
    const float* tgt_feats = (const float*)d_in[3];
    const int* corr    = (const int*)d_in[4];
    const float* rot   = (const float*)d_in[5];
    const float* trans = (const float*)d_in[6];
    float* out = (float*)d_out;

    gather_kernel<<<NUM_NODE * 32 / 256, 256>>>(src_pcd, tgt_pcd, src_feats, tgt_feats,
                                                corr, rot, trans);
    dim3 grid(NTILE, NTILE);   // (j-tiles, i-tiles)
    mma_pair_kernel<<<grid, 128>>>();
    reduce1_kernel<<<NUM_NODE / 256, 256>>>();
    reduce2_kernel<<<1, 32>>>(out);
}

// round 7
// speedup vs baseline: 3.7621x; 1.3060x over previous
#include <cuda_runtime.h>
#include <cuda_bf16.h>
#include <cstdint>

#define NUM_NODE 8192
#define N_PTS_MAX 20000
#define FEAT_DIM 32
#define TILE 128
#define NTILE (NUM_NODE / TILE)   // 64 -> grid 64x64
#define WPAD 17                   // smem row stride in 32-bit words (16 data + 1)

#define POS_R2 (0.0375f * 0.0375f)
#define NEG_R2 (0.1f * 0.1f)
#define EPSV 1e-7f
#define BIG2 1e10f                // sqrtf(1e10f + eps) == 100000.0f exactly

typedef unsigned long long ull;

#define FMA2(d, a, b, c) asm("fma.rn.f32x2 %0, %1, %2, %3;" : "=l"(d) : "l"(a), "l"(b), "l"(c))
#define ADD2(d, a, b)    asm("add.rn.f32x2 %0, %1, %2;"     : "=l"(d) : "l"(a), "l"(b))
#define MUL2(d, a, b)    asm("mul.rn.f32x2 %0, %1, %2;"     : "=l"(d) : "l"(a), "l"(b))
#define PACK2(d, lo, hi) asm("mov.b64 %0, {%1, %2};" : "=l"(d) : "f"(lo), "f"(hi))
#define UNPACK2(lo, hi, s) asm("mov.b64 {%0, %1}, %2;" : "=f"(lo), "=f"(hi) : "l"(s))

// -------- scratch (allocation-free: __device__ globals) --------
__device__ uint32_t g_sfw[NUM_NODE * FEAT_DIM / 2];  // src feats, bf16x2 packed (k,k+1)
__device__ uint32_t g_tfw[NUM_NODE * FEAT_DIM / 2];  // tgt feats, bf16x2 packed
__device__ float4   g_sp[NUM_NODE];                  // src pt xyz (rot applied), w = |feat|^2 exact
__device__ float4   g_tp2[NUM_NODE * 2];             // tgt pt duplicated: (x,x,y,y),(z,z,w,w)
__device__ int      g_rowmax[NUM_NODE];              // int-encoded non-neg float
__device__ int      g_rowmin[NUM_NODE];

// ---------------- kernel 1: warp-per-node gather (+ bf16 pack + row init) ----------------
__global__ void gather_kernel(const float* __restrict__ src_pcd,
                              const float* __restrict__ tgt_pcd,
                              const float* __restrict__ src_feats,
                              const float* __restrict__ tgt_feats,
                              const int* __restrict__ corr,
                              const float* __restrict__ rot,
                              const float* __restrict__ trans) {
    int node = (blockIdx.x * blockDim.x + threadIdx.x) >> 5;
    int lane = threadIdx.x & 31;
    if (node >= NUM_NODE) return;
    int ci = corr[2 * node + 0];
    int cj = corr[2 * node + 1];
    ci = min(max(ci, 0), N_PTS_MAX - 1);
    cj = min(max(cj, 0), N_PTS_MAX - 1);

    float fs = src_feats[ci * FEAT_DIM + lane];
    float ft = tgt_feats[cj * FEAT_DIM + lane];

    // pack (even k, odd k) bf16 pairs; even lanes write
    uint32_t sb = (uint32_t)__bfloat16_as_ushort(__float2bfloat16(fs));
    uint32_t tb = (uint32_t)__bfloat16_as_ushort(__float2bfloat16(ft));
    uint32_t snb = __shfl_down_sync(0xffffffffu, sb, 1);
    uint32_t tnb = __shfl_down_sync(0xffffffffu, tb, 1);
    if ((lane & 1) == 0) {
        g_sfw[node * (FEAT_DIM / 2) + (lane >> 1)] = sb | (snb << 16);
        g_tfw[node * (FEAT_DIM / 2) + (lane >> 1)] = tb | (tnb << 16);
    }

    // norms from EXACT fp32 values
    float sn = fs * fs, tn = ft * ft;
#pragma unroll
    for (int off = 16; off > 0; off >>= 1) {
        sn += __shfl_xor_sync(0xffffffffu, sn, off);
        tn += __shfl_xor_sync(0xffffffffu, tn, off);
    }

    if (lane == 0) {
        float x = src_pcd[3 * ci + 0];
        float y = src_pcd[3 * ci + 1];
        float z = src_pcd[3 * ci + 2];
        float tx = rot[0] * x + rot[1] * y + rot[2] * z + trans[0];
        float ty = rot[3] * x + rot[4] * y + rot[5] * z + trans[1];
        float tz = rot[6] * x + rot[7] * y + rot[8] * z + trans[2];
        g_sp[node] = make_float4(tx, ty, tz, sn);

        float gx = tgt_pcd[3 * cj + 0];
        float gy = tgt_pcd[3 * cj + 1];
        float gz = tgt_pcd[3 * cj + 2];
        g_tp2[2 * node + 0] = make_float4(gx, gx, gy, gy);
        g_tp2[2 * node + 1] = make_float4(gz, gz, tn, tn);

        g_rowmax[node] = 0;                       // bits of +0.0f
        g_rowmin[node] = __float_as_int(BIG2);
    }
}

// ---------------- kernel 2: bf16 mma Gram tile + hardest-mining epilogue ----------------
__global__ __launch_bounds__(128) void mma_pair_kernel() {
    __shared__ uint32_t sAw[TILE * WPAD];      // 8.5 KB
    __shared__ uint32_t sBw[TILE * WPAD];      // 8.5 KB
    __shared__ ulonglong2 sTPd[TILE * 2];      // 4 KB duplicated tgt pts

    const int t  = threadIdx.x;
    const int w  = t >> 5;
    const int l  = t & 31;
    const int g  = l >> 2;        // row/col group (0..7)
    const int tq = l & 3;         // thread-in-quad (0..3)
    const int i0 = blockIdx.y * TILE;
    const int j0 = blockIdx.x * TILE;

    // ---- stage tiles (32-bit LDG/STS; coalesced gmem, stride-17 smem) ----
    {
        const uint32_t* gA = &g_sfw[i0 * (FEAT_DIM / 2)];
        const uint32_t* gB = &g_tfw[j0 * (FEAT_DIM / 2)];
#pragma unroll
        for (int v = t; v < TILE * 16; v += 128) {
            int row = v >> 4, c = v & 15;
            sAw[row * WPAD + c] = gA[v];
            sBw[row * WPAD + c] = gB[v];
        }
        const ulonglong2* ps = reinterpret_cast<const ulonglong2*>(&g_tp2[2 * j0]);
        for (int v = t; v < TILE * 2; v += 128) sTPd[v] = ps[v];
    }
    __syncthreads();

    // ---- MMA: warp w owns rows [w*32, w*32+32), all 128 cols ----
    float acc[2][16][4];
#pragma unroll
    for (int mf = 0; mf < 2; mf++)
#pragma unroll
        for (int nf = 0; nf < 16; nf++)
#pragma unroll
            for (int r = 0; r < 4; r++) acc[mf][nf][r] = 0.f;

    const int rbase = w * 32;
#pragma unroll
    for (int ks = 0; ks < 2; ks++) {          // K = 32 = 2 x k16
        const int kw = ks * 8;                 // word offset of this K-step
        uint32_t a[2][4];
#pragma unroll
        for (int mf = 0; mf < 2; mf++) {
            int r0 = rbase + mf * 16 + g;
            a[mf][0] = sAw[r0 * WPAD + kw + tq];
            a[mf][1] = sAw[(r0 + 8) * WPAD + kw + tq];
            a[mf][2] = sAw[r0 * WPAD + kw + tq + 4];
            a[mf][3] = sAw[(r0 + 8) * WPAD + kw + tq + 4];
        }
#pragma unroll
        for (int nf = 0; nf < 16; nf++) {
            int jr = nf * 8 + g;
            uint32_t b0 = sBw[jr * WPAD + kw + tq];
            uint32_t b1 = sBw[jr * WPAD + kw + tq + 4];
#pragma unroll
            for (int mf = 0; mf < 2; mf++) {
                asm volatile(
                    "mma.sync.aligned.m16n8k16.row.col.f32.bf16.bf16.f32 "
                    "{%0,%1,%2,%3}, {%4,%5,%6,%7}, {%8,%9}, {%0,%1,%2,%3};"
                    : "+f"(acc[mf][nf][0]), "+f"(acc[mf][nf][1]),
                      "+f"(acc[mf][nf][2]), "+f"(acc[mf][nf][3])
                    : "r"(a[mf][0]), "r"(a[mf][1]), "r"(a[mf][2]), "r"(a[mf][3]),
                      "r"(b0), "r"(b1));
            }
        }
    }

    // ---- epilogue: exact fp32 point masks + d2f from Gram values ----
    ull npx2[2], npy2[2], npz2[2], sn2[2];
#pragma unroll
    for (int mf = 0; mf < 2; mf++) {
        float4 spA = g_sp[i0 + rbase + mf * 16 + g];
        float4 spB = g_sp[i0 + rbase + mf * 16 + g + 8];
        PACK2(npx2[mf], -spA.x, -spB.x);
        PACK2(npy2[mf], -spA.y, -spB.y);
        PACK2(npz2[mf], -spA.z, -spB.z);
        PACK2(sn2[mf], spA.w, spB.w);
    }
    ull m2; PACK2(m2, -2.f, -2.f);

    float mp[4] = {0.f, 0.f, 0.f, 0.f};
    float mn[4] = {BIG2, BIG2, BIG2, BIG2};

#pragma unroll
    for (int nf = 0; nf < 16; nf++) {
#pragma unroll
        for (int sub = 0; sub < 2; sub++) {
            int col = nf * 8 + tq * 2 + sub;
            ulonglong2 qa = sTPd[2 * col];       // (x,x),(y,y)
            ulonglong2 qb = sTPd[2 * col + 1];   // (z,z),(w,w)
#pragma unroll
            for (int mf = 0; mf < 2; mf++) {
                ull G2; PACK2(G2, acc[mf][nf][sub], acc[mf][nf][2 + sub]);
                ull dx2, dy2, dz2, d2p2, sntn2, d2f2;
                ADD2(dx2, qa.x, npx2[mf]);
                ADD2(dy2, qa.y, npy2[mf]);
                ADD2(dz2, qb.x, npz2[mf]);
                MUL2(d2p2, dx2, dx2);
                FMA2(d2p2, dy2, dy2, d2p2);
                FMA2(d2p2, dz2, dz2, d2p2);
                ADD2(sntn2, sn2[mf], qb.y);
                FMA2(d2f2, m2, G2, sntn2);
                float p0, p1, f0, f1;
                UNPACK2(p0, p1, d2p2);
                UNPACK2(f0, f1, d2f2);
                mp[2 * mf]     = fmaxf(mp[2 * mf],     p0 < POS_R2 ? f0 : 0.f);
                mn[2 * mf]     = fminf(mn[2 * mf],     p0 > NEG_R2 ? f0 : BIG2);
                mp[2 * mf + 1] = fmaxf(mp[2 * mf + 1], p1 < POS_R2 ? f1 : 0.f);
                mn[2 * mf + 1] = fminf(mn[2 * mf + 1], p1 > NEG_R2 ? f1 : BIG2);
            }
        }
    }

    // quad-reduce across the 4 lanes sharing the same rows, then atomic row-reduce.
    // All values clamped non-negative -> int ordering == float ordering -> deterministic.
#pragma unroll
    for (int q = 0; q < 4; q++) {
        mp[q] = fmaxf(mp[q], __shfl_xor_sync(0xffffffffu, mp[q], 1));
        mp[q] = fmaxf(mp[q], __shfl_xor_sync(0xffffffffu, mp[q], 2));
        mn[q] = fminf(mn[q], __shfl_xor_sync(0xffffffffu, mn[q], 1));
        mn[q] = fminf(mn[q], __shfl_xor_sync(0xffffffffu, mn[q], 2));
    }
    if (tq == 0) {
#pragma unroll
        for (int q = 0; q < 4; q++) {
            int mf = q >> 1;
            int row = i0 + rbase + mf * 16 + g + (q & 1) * 8;
            atomicMax(&g_rowmax[row], __float_as_int(fmaxf(mp[q], 0.f)));
            atomicMin(&g_rowmin[row], __float_as_int(fmaxf(mn[q], 0.f)));
        }
    }
}

// ---------------- kernel 3: final loss (one block, deterministic order) ----------------
__global__ __launch_bounds__(1024) void loss_kernel(float* __restrict__ out) {
    __shared__ float ssum[1024];
    const int t = threadIdx.x;
    float acc = 0.f;
#pragma unroll
    for (int r = t; r < NUM_NODE; r += 1024) {
        float mp = __int_as_float(g_rowmax[r]);
        float mn = __int_as_float(g_rowmin[r]);
        float fp = sqrtf(mp + EPSV);
        float cn = sqrtf(mn + EPSV);
        acc += fmaxf(fp - 0.1f, 0.f) + fmaxf(1.4f - cn, 0.f);
    }
    ssum[t] = acc;
    __syncthreads();
#pragma unroll
    for (int off = 512; off > 0; off >>= 1) {
        if (t < off) ssum[t] += ssum[t + off];
        __syncthreads();
    }
    if (t == 0) out[0] = ssum[0] / (float)NUM_NODE;
}

extern "C" void kernel_launch(void* const* d_in, const int* in_sizes, int n_in,
                              void* d_out, int out_size) {
    const float* src_pcd  = (const float*)d_in[0];
    const float* tgt_pcd  = (const float*)d_in[1];
    const float* src_feats = (const float*)d_in[2];
    const float* tgt_feats = (const float*)d_in[3];
    const int* corr    = (const int*)d_in[4];
    const float* rot   = (const float*)d_in[5];
    const float* trans = (const float*)d_in[6];
    float* out = (float*)d_out;

    gather_kernel<<<NUM_NODE * 32 / 256, 256>>>(src_pcd, tgt_pcd, src_feats, tgt_feats,
                                                corr, rot, trans);
    dim3 grid(NTILE, NTILE);   // (j-tiles, i-tiles)
    mma_pair_kernel<<<grid, 128>>>();
    loss_kernel<<<1, 1024>>>(out);
}